// round 17
// baseline (speedup 1.0000x reference)
#include <cuda_runtime.h>
#include <cuda_bf16.h>
#include <limits.h>

// Scratch for per-batch chirp metadata (generic fallback path only).
#define MAX_BN (32 * 256)
__device__ int g_sn[MAX_BN];
__device__ int g_en[MAX_BN];
__device__ int g_s0[MAX_BN];
__device__ int g_e0[MAX_BN];

// ---------------------------------------------------------------------------
// Kernel 1 (generic fallback): per-batch prefix scan over chirp widths.
// ---------------------------------------------------------------------------
__global__ void tb_meta_kernel(const int* __restrict__ xi,
                               const int* __restrict__ Narr,
                               float* __restrict__ out_xi,
                               int n_max)
{
    extern __shared__ int sh[];
    const int b = blockIdx.x;
    const int i = threadIdx.x;

    const int s0 = xi[(b * n_max + i) * 2 + 0];
    const int e0 = xi[(b * n_max + i) * 2 + 1];
    const int Nb = Narr[b];
    const bool valid = (i < Nb);

    int w = e0 - s0;
    if (w < 0) w = 0;
    const int wv = valid ? w : 0;

    sh[i] = wv;
    __syncthreads();
    for (int off = 1; off < n_max; off <<= 1) {
        int v = (i >= off) ? sh[i - off] : 0;
        __syncthreads();
        sh[i] += v;
        __syncthreads();
    }
    const int csum = sh[i];

    const int sn = csum - wv + i;
    const int en = csum + i;

    const int base = b * n_max + i;
    g_sn[base] = sn;
    g_en[base] = en;
    g_s0[base] = s0;
    g_e0[base] = e0;

    out_xi[base * 2 + 0] = valid ? (float)sn : 0.0f;
    out_xi[base * 2 + 1] = valid ? (float)en : 0.0f;
}

// ---------------------------------------------------------------------------
// Column classification from smem metadata (binary search; fallback path).
// ---------------------------------------------------------------------------
template<int NMAX>
__device__ __forceinline__ void classify(
    const int* s_sn, const int* s_en, const int* s_s0, const int* s_e0,
    int Nb, int t, int W,
    bool& in_chirp, bool& is_sep, int& src)
{
    int lo = 0, hi = NMAX;
    #pragma unroll
    for (int step = 0; step < 31; step++) {
        if (lo >= hi) break;
        const int mid = (lo + hi) >> 1;
        const int e = (mid < Nb) ? s_en[mid] : INT_MAX;
        if (e <= t) lo = mid + 1; else hi = mid;
    }
    const int i = lo;
    const int ic = min(i, NMAX - 1);

    const int sn_i = s_sn[ic];
    const int en_i = s_en[ic];
    const int s0_i = s_s0[ic];
    const int e0_i = s_e0[ic];

    in_chirp = (i < Nb) && (t >= sn_i) && (en_i > sn_i) && (e0_i > s0_i);
    src = min(max(s0_i + (t - sn_i), 0), W - 1);

    const int jp = min(max(i - 1, 0), NMAX - 1);
    const int en_prev = s_en[jp];
    is_sep = (i >= 1) && (t == en_prev) && ((i - 1) < (Nb - 1)) && (en_prev < W);
}

// ---------------------------------------------------------------------------
// Row-per-block specialized kernel with ALIGNED float4 stores.
// grid = B*ROWS blocks (2048), block = 256 threads; each block owns ONE
// output row (contiguous WOUTC floats). Per-row alignment phase ph makes all
// vector stores 16B-aligned STG.128 (store-issue cost /1.7, zero partial
// sectors). Classification: closed form w/ magic-multiply division when xi
// is uniform (verified per-warp); smem scan + binary search otherwise.
// ---------------------------------------------------------------------------
template<int ROWS, int WC, int WOUTC, int NMAX>
__global__ __launch_bounds__(256, 6)
void tb_row_tpl(const float* __restrict__ x,
                const int* __restrict__ xi,
                const int* __restrict__ xl,
                const float* __restrict__ sep_param,
                const int* __restrict__ Narr,
                float* __restrict__ out_x,
                float* __restrict__ out_xi,
                float* __restrict__ out_xl)
{
    static_assert(NMAX == 128 && ROWS == 128, "sized for 128");
    __shared__ int s_sn[NMAX], s_en[NMAX], s_s0[NMAX], s_e0[NMAX];

    const int blk = blockIdx.x;
    const int b = blk >> 7;            // / ROWS
    const int r = blk & 127;           // % ROWS
    const int tid = threadIdx.x;
    const int lane = tid & 31;
    const bool emit = (r == 0);

    // ---- every warp: load 4 chirps/lane from xi, test uniformity ----
    const int Nb = __ldg(&Narr[b]);
    const int4* xi4 = (const int4*)(xi + (b * NMAX + lane * 4) * 2);
    const int4 q0 = __ldg(&xi4[0]);
    const int4 q1 = __ldg(&xi4[1]);
    int s0v[4] = {q0.x, q0.z, q1.x, q1.z};
    int e0v[4] = {q0.y, q0.w, q1.y, q1.w};

    const int s0_0 = __shfl_sync(0xffffffffu, s0v[0], 0);
    const int s0_1 = __shfl_sync(0xffffffffu, s0v[1], 0);
    const int w0   = __shfl_sync(0xffffffffu, e0v[0] - s0v[0], 0);
    const int step = s0_1 - s0_0;

    bool okc = (w0 > 0);
    #pragma unroll
    for (int k = 0; k < 4; k++) {
        const int idx = lane * 4 + k;
        okc = okc && (e0v[k] - s0v[k] == w0)
                  && (s0v[k] == s0_0 + idx * step);
    }
    const bool uniform = __all_sync(0xffffffffu, okc);

    const int P = w0 + 1;
    const unsigned magic = uniform ? (0xFFFFFFFFu / (unsigned)P + 1u) : 0u;

    if (uniform) {
        if (emit && tid < NMAX) {
            const bool valid = (tid < Nb);
            const int sn = tid * P;
            out_xi[(b * NMAX + tid) * 2 + 0] = valid ? (float)sn : 0.0f;
            out_xi[(b * NMAX + tid) * 2 + 1] = valid ? (float)(sn + w0) : 0.0f;
        }
    } else {
        // warp0 shfl-scan -> smem (block-uniform branch, barrier safe)
        if (tid < 32) {
            int wv[4], pre[4];
            int run = 0;
            #pragma unroll
            for (int k = 0; k < 4; k++) {
                const int idx = lane * 4 + k;
                int w = e0v[k] - s0v[k];
                if (w < 0) w = 0;
                wv[k] = (idx < Nb) ? w : 0;
                run += wv[k];
                pre[k] = run;
            }
            int tot = run;
            #pragma unroll
            for (int off = 1; off < 32; off <<= 1) {
                int v = __shfl_up_sync(0xffffffffu, tot, off);
                if (lane >= off) tot += v;
            }
            const int base = tot - run;
            #pragma unroll
            for (int k = 0; k < 4; k++) {
                const int idx = lane * 4 + k;
                const int csum = base + pre[k];
                const int sn = csum - wv[k] + idx;
                const int en = csum + idx;
                s_sn[idx] = sn;
                s_en[idx] = en;
                s_s0[idx] = s0v[k];
                s_e0[idx] = e0v[k];
                if (emit) {
                    const bool valid = (idx < Nb);
                    out_xi[(b * NMAX + idx) * 2 + 0] = valid ? (float)sn : 0.0f;
                    out_xi[(b * NMAX + idx) * 2 + 1] = valid ? (float)en : 0.0f;
                }
            }
        }
        __syncthreads();
    }

    const float sepval = __ldg(sep_param);

    // classification helper (uniform branch is warp/block-uniform)
    auto cls = [&](int t, bool& inc, bool& sep, int& src) {
        if (uniform) {
            const unsigned c = __umulhi((unsigned)(t + 1), magic);
            const int i = min((int)c, Nb);
            const int rem = t - i * P;
            inc = (i < Nb) && (rem >= 0);
            sep = (rem == -1) && (i < Nb) && (t < WC);
            src = min(max(s0_0 + i * step + rem, 0), WC - 1);
        } else {
            classify<NMAX>(s_sn, s_en, s_s0, s_e0, Nb, t, WC, inc, sep, src);
        }
    };

    const float* __restrict__ xrow = x + (size_t)(b * ROWS + r) * WC;
    const size_t rowbase = (size_t)(b * ROWS + r) * WOUTC;
    float* __restrict__ orow = out_x + rowbase;

    const int ph = (int)((4 - (rowbase & 3)) & 3);     // scalar head count
    const int n4 = (WOUTC - ph) >> 2;                  // aligned float4 count
    const int tstart = ph + n4 * 4;                    // tail start

    // vector body: 16B-aligned STG.128
    for (int g = tid; g < n4; g += 256) {
        const int t0 = ph + g * 4;
        float v0, v1, v2, v3;
        bool inc, sep; int src;
        cls(t0 + 0, inc, sep, src);
        v0 = inc ? __ldg(&xrow[src]) : (sep ? sepval : 0.0f);
        cls(t0 + 1, inc, sep, src);
        v1 = inc ? __ldg(&xrow[src]) : (sep ? sepval : 0.0f);
        cls(t0 + 2, inc, sep, src);
        v2 = inc ? __ldg(&xrow[src]) : (sep ? sepval : 0.0f);
        cls(t0 + 3, inc, sep, src);
        v3 = inc ? __ldg(&xrow[src]) : (sep ? sepval : 0.0f);
        *reinterpret_cast<float4*>(orow + t0) = make_float4(v0, v1, v2, v3);
    }

    // scalar head [0, ph)
    if (tid < ph) {
        const int t = tid;
        bool inc, sep; int src;
        cls(t, inc, sep, src);
        orow[t] = inc ? __ldg(&xrow[src]) : (sep ? sepval : 0.0f);
    }
    // scalar tail [tstart, WOUTC)  (use a different warp than the head)
    if (tid >= 32 && tid < 32 + (WOUTC - tstart)) {
        const int t = tstart + (tid - 32);
        bool inc, sep; int src;
        cls(t, inc, sep, src);
        orow[t] = inc ? __ldg(&xrow[src]) : (sep ? sepval : 0.0f);
    }

    // xl row (one block per batch: r == 0)
    if (emit) {
        for (int t = tid; t < WOUTC; t += 256) {
            bool inc, sep; int src;
            cls(t, inc, sep, src);
            const int xlv = inc ? __ldg(&xl[b * WC + src]) : (sep ? 2 : 0);
            out_xl[(size_t)b * WOUTC + t] = (float)xlv;
        }
    }
}

// ---------------------------------------------------------------------------
// Generic fallback main kernel (two-launch path, unchanged).
// ---------------------------------------------------------------------------
__global__ __launch_bounds__(256, 6)
void tb_main_kernel(const float* __restrict__ x,
                    const int* __restrict__ xl,
                    const float* __restrict__ sep_param,
                    const int* __restrict__ Narr,
                    float* __restrict__ out_x,
                    float* __restrict__ out_xl,
                    int rows, int W, int w_out, int n_max)
{
    __shared__ int s_sn[256], s_en[256], s_s0[256], s_e0[256];
    __shared__ int s_Nb;

    const int b = blockIdx.y;
    const int tid = threadIdx.y * blockDim.x + threadIdx.x;

    if (tid < n_max) {
        const int base = b * n_max + tid;
        s_sn[tid] = g_sn[base];
        s_en[tid] = g_en[base];
        s_s0[tid] = g_s0[base];
        s_e0[tid] = g_e0[base];
    }
    if (tid == 0) s_Nb = Narr[b];
    __syncthreads();

    const int t = blockIdx.x * blockDim.x + threadIdx.x;
    if (t >= w_out) return;

    const int Nb = s_Nb;
    int lo = 0, hi = n_max;
    while (lo < hi) {
        const int mid = (lo + hi) >> 1;
        const int e = (mid < Nb) ? s_en[mid] : INT_MAX;
        if (e <= t) lo = mid + 1; else hi = mid;
    }
    const int i = lo;
    const int ic = min(i, n_max - 1);
    const int sn_i = s_sn[ic], en_i = s_en[ic];
    const int s0_i = s_s0[ic], e0_i = s_e0[ic];
    const bool in_chirp = (i < Nb) && (t >= sn_i) && (en_i > sn_i) && (e0_i > s0_i);
    int src = min(max(s0_i + (t - sn_i), 0), W - 1);
    const int jp = min(max(i - 1, 0), n_max - 1);
    const int en_prev = s_en[jp];
    const bool is_sep = (i >= 1) && (t == en_prev) && ((i - 1) < (Nb - 1)) && (en_prev < W);
    const float fill = is_sep ? sep_param[0] : 0.0f;

    const float* __restrict__ xcol = x + (size_t)b * rows * W + src;
    float* __restrict__ ocol = out_x + (size_t)b * rows * w_out + t;
    const int ystep = blockDim.y;

    if (in_chirp) {
        int h = threadIdx.y;
        for (; h + 7 * ystep < rows; h += 8 * ystep) {
            float v[8];
            #pragma unroll
            for (int k = 0; k < 8; k++)
                v[k] = __ldg(xcol + (size_t)(h + k * ystep) * W);
            #pragma unroll
            for (int k = 0; k < 8; k++)
                ocol[(size_t)(h + k * ystep) * w_out] = v[k];
        }
        for (; h < rows; h += ystep)
            ocol[(size_t)h * w_out] = __ldg(xcol + (size_t)h * W);
    } else {
        for (int h = threadIdx.y; h < rows; h += ystep)
            ocol[(size_t)h * w_out] = fill;
    }

    if (threadIdx.y == 0) {
        int xlv = in_chirp ? xl[b * W + src] : (is_sep ? 2 : 0);
        out_xl[(size_t)b * w_out + t] = (float)xlv;
    }
}

// ---------------------------------------------------------------------------
// Launch.
// ---------------------------------------------------------------------------
extern "C" void kernel_launch(void* const* d_in, const int* in_sizes, int n_in,
                              void* d_out, int out_size)
{
    const float* x   = (const float*)d_in[0];
    const int*   xi  = (const int*)  d_in[1];
    const int*   Nn  = (const int*)  d_in[2];
    const int*   xl  = (const int*)  d_in[3];
    const float* sep = (const float*)d_in[4];

    const int B     = in_sizes[2];
    const int n_max = in_sizes[1] / (2 * B);
    const int W     = in_sizes[3] / B;
    const int rows  = in_sizes[0] / (B * W);           // C * H
    const int w_out = (out_size - B * n_max * 2) / (B * (rows + 1));

    float* out_x  = (float*)d_out;
    float* out_xi = out_x + (size_t)B * rows * w_out;
    float* out_xl = out_xi + (size_t)B * n_max * 2;

    if (rows == 128 && W == 8192 && w_out == 6271 && n_max == 128) {
        tb_row_tpl<128, 8192, 6271, 128><<<B * 128, 256>>>(
            x, xi, xl, sep, Nn, out_x, out_xi, out_xl);
    } else {
        tb_meta_kernel<<<B, n_max, n_max * sizeof(int)>>>(xi, Nn, out_xi, n_max);
        dim3 block(128, 2);
        dim3 grid((w_out + 127) / 128, B);
        tb_main_kernel<<<grid, block>>>(x, xl, sep, Nn, out_x, out_xl,
                                        rows, W, w_out, n_max);
    }
}